// round 15
// baseline (speedup 1.0000x reference)
#include <cuda_runtime.h>

#define D 64
#define NCAP 100000
#define ECAP 1600000
#define GCAP 128
#define LCAP 8
#define BN_EPS 1e-5f

// ---------------- device scratch ----------------
__device__ int   g_degcnt[NCAP];
__device__ int   g_off[NCAP + 1];
__device__ int   g_cur[NCAP];
__device__ int   g_csr[ECAP];
__device__ float g_invdeg[NCAP];
__device__ float g_gcnt[GCAP];
__device__ float g_invg[GCAP];
__device__ float g_h[NCAP * D];
__device__ float g_z[NCAP * D];
__device__ float g_statsall[LCAP * 2 * D];
__device__ int   g_bsum[128];

// ---------------- init: zero counters + stats + g_pool; off[n]=e ----------
__global__ void k_init(int n, int g, int L, int e, float* __restrict__ gp) {
    int i = blockIdx.x * blockDim.x + threadIdx.x;
    if (i < n) g_degcnt[i] = 0;
    if (i < g) g_gcnt[i] = 0.0f;
    if (i < g * D) gp[i] = 0.0f;
    if (i < L * 2 * D) g_statsall[i] = 0.0f;
    if (i == 0) g_off[n] = e;
}

// ---------------- fused histogram: in-degree + graph counts ----------------
__global__ void k_degcnt(const int* __restrict__ dst, const int* __restrict__ batch,
                         int e, int n) {
    int i = blockIdx.x * blockDim.x + threadIdx.x;
    if (i < e) atomicAdd(&g_degcnt[dst[i]], 1);
    if (i < n) atomicAdd(&g_gcnt[batch[i]], 1.0f);
}

// ---------------- scan pass 1: per-block reduce (1024/block) + invg -------
__global__ __launch_bounds__(256) void k_scan1(int n, int g) {
    int tid = threadIdx.x;
    int i0  = blockIdx.x * 1024 + tid * 4;
    int s = 0;
#pragma unroll
    for (int k = 0; k < 4; k++) {
        int i = i0 + k;
        if (i < n) s += g_degcnt[i];
    }
#pragma unroll
    for (int o = 16; o > 0; o >>= 1) s += __shfl_down_sync(0xffffffffu, s, o);
    __shared__ int ws[8];
    if ((tid & 31) == 0) ws[tid >> 5] = s;
    __syncthreads();
    if (tid == 0) {
        int t = 0;
#pragma unroll
        for (int k = 0; k < 8; k++) t += ws[k];
        g_bsum[blockIdx.x] = t;
    }
    if (blockIdx.x == 0 && tid < g) g_invg[tid] = 1.0f / fmaxf(g_gcnt[tid], 1.0f);
}

// ---------------- scan pass 2 (fused): local scan + inline predecessor sum
__global__ __launch_bounds__(256) void k_scan3(int n, int nblk) {
    int tid = threadIdx.x, lane = tid & 31, wid = tid >> 5;

    __shared__ int sPred;
    {
        int v = (tid < nblk && tid < blockIdx.x) ? g_bsum[tid] : 0;
#pragma unroll
        for (int o = 16; o > 0; o >>= 1) v += __shfl_down_sync(0xffffffffu, v, o);
        __shared__ int pw[8];
        if (lane == 0) pw[wid] = v;
        __syncthreads();
        if (tid == 0) {
            int t = 0;
#pragma unroll
            for (int k = 0; k < 8; k++) t += pw[k];
            sPred = t;
        }
    }

    int i0 = blockIdx.x * 1024 + tid * 4;
    int v[4];
#pragma unroll
    for (int k = 0; k < 4; k++) {
        int i = i0 + k;
        v[k] = (i < n) ? g_degcnt[i] : 0;
    }
    int s  = v[0] + v[1] + v[2] + v[3];
    int sc = s;
#pragma unroll
    for (int o = 1; o < 32; o <<= 1) {
        int t = __shfl_up_sync(0xffffffffu, sc, o);
        if (lane >= o) sc += t;
    }
    __shared__ int ws[8];
    if (lane == 31) ws[wid] = sc;
    __syncthreads();
    if (wid == 0) {
        int t = (lane < 8) ? ws[lane] : 0;
#pragma unroll
        for (int o = 1; o < 8; o <<= 1) {
            int u = __shfl_up_sync(0xffffffffu, t, o);
            if (lane >= o) t += u;
        }
        if (lane < 8) ws[lane] = t;
    }
    __syncthreads();
    int base = sPred + (wid ? ws[wid - 1] : 0) + (sc - s);
#pragma unroll
    for (int k = 0; k < 4; k++) {
        int i = i0 + k;
        if (i < n) {
            g_off[i]    = base;
            g_cur[i]    = base;
            g_invdeg[i] = 1.0f / fmaxf((float)v[k], 1.0f);
            base += v[k];
        }
    }
}

__global__ void k_scatter(const int* __restrict__ src, const int* __restrict__ dst, int e) {
    int i = blockIdx.x * blockDim.x + threadIdx.x;
    if (i < e) {
        int pos    = atomicAdd(&g_cur[dst[i]], 1);
        g_csr[pos] = src[i];
    }
}

// ---------------- GEMM0 fused: agg + GEMM + bias + BN stats ---------------
// R11-exact except the inner edge loop uses a 2-way unroll: two independent
// load buffers + accumulators -> 2 outstanding LDGs per warp (MLP 2).
__global__ __launch_bounds__(256) void k_gemm0(const float* __restrict__ x,
                                               const float* __restrict__ W,
                                               const float* __restrict__ bias,
                                               int first, int layer, int n) {
    __shared__ float sW[64 * 64];
    __shared__ float sX[64 * 68];
    int tid  = threadIdx.x;
    int brow = blockIdx.x * 64;
    int lane = tid & 31, wrp = tid >> 5;
    const float* __restrict__ hin = first ? x : (const float*)g_h;  // device-side
    float* __restrict__ stats = g_statsall + layer * 2 * D;         // device-side
    const unsigned m = 0xffffffffu;

    // stage W (coalesced)
    {
        const float4* W4 = (const float4*)W;
        float4* sW4      = (float4*)sW;
#pragma unroll
        for (int e = tid; e < 1024; e += 256) sW4[e] = W4[e];
    }

    // fused aggregation staging: warp handles 8 rows, lane owns 2 columns
    const float2* h2 = (const float2*)hin;
#pragma unroll 1
    for (int rr = 0; rr < 8; rr++) {
        int r   = wrp * 8 + rr;
        int row = brow + r;
        float2 a = make_float2(0.f, 0.f);
        float2 b = make_float2(0.f, 0.f);
        if (row < n) {
            int beg = g_off[row], end = g_off[row + 1];
#pragma unroll 1
            for (int jb = beg; jb < end; jb += 32) {
                int cnt = end - jb;
                if (cnt > 32) cnt = 32;
                int sv = (lane < cnt) ? g_csr[jb + lane] : 0;
                int k = 0;
#pragma unroll 1
                for (; k + 2 <= cnt; k += 2) {
                    int s0 = __shfl_sync(m, sv, k);
                    int s1 = __shfl_sync(m, sv, k + 1);
                    float2 v0 = h2[s0 * 32 + lane];
                    float2 v1 = h2[s1 * 32 + lane];
                    a.x += v0.x; a.y += v0.y;
                    b.x += v1.x; b.y += v1.y;
                }
                if (k < cnt) {
                    int s    = __shfl_sync(m, sv, k);
                    float2 v = h2[s * 32 + lane];
                    a.x += v.x; a.y += v.y;
                }
            }
            float inv = g_invdeg[row];
            float2 hv = h2[row * 32 + lane];
            a.x = hv.x + (a.x + b.x) * inv;
            a.y = hv.y + (a.y + b.y) * inv;
        }
        sX[(2 * lane) * 68 + r]     = a.x;
        sX[(2 * lane + 1) * 68 + r] = a.y;
    }
    __syncthreads();

    int tx = tid & 15, ty = tid >> 4;
    float4 a0 = make_float4(0.f, 0.f, 0.f, 0.f), a1 = a0, a2 = a0, a3 = a0;
#pragma unroll
    for (int k = 0; k < 64; k++) {
        float4 w  = *(const float4*)&sW[k * 64 + tx * 4];
        float4 xv = *(const float4*)&sX[k * 68 + ty * 4];
        a0.x = fmaf(xv.x, w.x, a0.x); a0.y = fmaf(xv.x, w.y, a0.y);
        a0.z = fmaf(xv.x, w.z, a0.z); a0.w = fmaf(xv.x, w.w, a0.w);
        a1.x = fmaf(xv.y, w.x, a1.x); a1.y = fmaf(xv.y, w.y, a1.y);
        a1.z = fmaf(xv.y, w.z, a1.z); a1.w = fmaf(xv.y, w.w, a1.w);
        a2.x = fmaf(xv.z, w.x, a2.x); a2.y = fmaf(xv.z, w.y, a2.y);
        a2.z = fmaf(xv.z, w.z, a2.z); a2.w = fmaf(xv.z, w.w, a2.w);
        a3.x = fmaf(xv.w, w.x, a3.x); a3.y = fmaf(xv.w, w.y, a3.y);
        a3.z = fmaf(xv.w, w.z, a3.z); a3.w = fmaf(xv.w, w.w, a3.w);
    }

    float4 bv = *(const float4*)(bias + tx * 4);
    float4 accs[4] = {a0, a1, a2, a3};
    float4 s = make_float4(0.f, 0.f, 0.f, 0.f);
    float4 q = make_float4(0.f, 0.f, 0.f, 0.f);
#pragma unroll
    for (int i = 0; i < 4; i++) {
        int r = brow + ty * 4 + i;
        if (r < n) {
            float4 o = accs[i];
            o.x += bv.x; o.y += bv.y; o.z += bv.z; o.w += bv.w;
            *(float4*)(g_z + r * D + tx * 4) = o;
            s.x += o.x; s.y += o.y; s.z += o.z; s.w += o.w;
            q.x = fmaf(o.x, o.x, q.x); q.y = fmaf(o.y, o.y, q.y);
            q.z = fmaf(o.z, o.z, q.z); q.w = fmaf(o.w, o.w, q.w);
        }
    }
    __syncthreads();
    *(float4*)&sW[ty * 64 + tx * 4] = s;   // reuse smem: [16][64] partial sums
    *(float4*)&sX[ty * 64 + tx * 4] = q;
    __syncthreads();
    if (tid < 64) {
        float S = 0.f, Q = 0.f;
#pragma unroll
        for (int k = 0; k < 16; k++) {
            S += sW[k * 64 + tid];
            Q += sX[k * 64 + tid];
        }
        atomicAdd(&stats[tid], S);
        atomicAdd(&stats[64 + tid], Q);
    }
}

// ---------------- GEMM1: h = relu(bn(z)) @ W2 + b2, pool epilogue --------
__global__ __launch_bounds__(256) void k_gemm1(const float* __restrict__ gamma,
                                               const float* __restrict__ beta,
                                               const float* __restrict__ W,
                                               const float* __restrict__ bias,
                                               float* __restrict__ pool,
                                               int layer, int n, int addflag) {
    __shared__ float sW[64 * 64];
    __shared__ float sX[64 * 68];
    __shared__ float sAB[2 * D];
    int tid  = threadIdx.x;
    int brow = blockIdx.x * 64;
    const float* __restrict__ stats = g_statsall + layer * 2 * D;  // device-side

    if (tid < 64) {
        float invN = 1.0f / (float)n;
        float mean = stats[tid] * invN;
        float var  = stats[64 + tid] * invN - mean * mean;
        float a    = gamma[tid] * rsqrtf(var + BN_EPS);
        sAB[tid]      = a;
        sAB[64 + tid] = beta[tid] - mean * a;
    }
    {
        const float4* W4 = (const float4*)W;
        float4* sW4      = (float4*)sW;
#pragma unroll
        for (int e = tid; e < 1024; e += 256) sW4[e] = W4[e];
    }
    __syncthreads();

    for (int e = tid; e < 1024; e += 256) {
        int r   = e & 63;
        int c4  = e >> 6;
        int row = brow + r;
        float4 v = make_float4(0.f, 0.f, 0.f, 0.f);
        if (row < n) v = *(const float4*)(g_z + row * D + c4 * 4);
        int c = c4 * 4;
        v.x = fmaxf(fmaf(v.x, sAB[c + 0], sAB[64 + c + 0]), 0.f);
        v.y = fmaxf(fmaf(v.y, sAB[c + 1], sAB[64 + c + 1]), 0.f);
        v.z = fmaxf(fmaf(v.z, sAB[c + 2], sAB[64 + c + 2]), 0.f);
        v.w = fmaxf(fmaf(v.w, sAB[c + 3], sAB[64 + c + 3]), 0.f);
        sX[(c + 0) * 68 + r] = v.x;
        sX[(c + 1) * 68 + r] = v.y;
        sX[(c + 2) * 68 + r] = v.z;
        sX[(c + 3) * 68 + r] = v.w;
    }
    __syncthreads();

    int tx = tid & 15, ty = tid >> 4;
    float4 a0 = make_float4(0.f, 0.f, 0.f, 0.f), a1 = a0, a2 = a0, a3 = a0;
#pragma unroll
    for (int k = 0; k < 64; k++) {
        float4 w  = *(const float4*)&sW[k * 64 + tx * 4];
        float4 xv = *(const float4*)&sX[k * 68 + ty * 4];
        a0.x = fmaf(xv.x, w.x, a0.x); a0.y = fmaf(xv.x, w.y, a0.y);
        a0.z = fmaf(xv.x, w.z, a0.z); a0.w = fmaf(xv.x, w.w, a0.w);
        a1.x = fmaf(xv.y, w.x, a1.x); a1.y = fmaf(xv.y, w.y, a1.y);
        a1.z = fmaf(xv.y, w.z, a1.z); a1.w = fmaf(xv.y, w.w, a1.w);
        a2.x = fmaf(xv.z, w.x, a2.x); a2.y = fmaf(xv.z, w.y, a2.y);
        a2.z = fmaf(xv.z, w.z, a2.z); a2.w = fmaf(xv.z, w.w, a2.w);
        a3.x = fmaf(xv.w, w.x, a3.x); a3.y = fmaf(xv.w, w.y, a3.y);
        a3.z = fmaf(xv.w, w.z, a3.z); a3.w = fmaf(xv.w, w.w, a3.w);
    }

    float4 bv = *(const float4*)(bias + tx * 4);
    float4 accs[4] = {a0, a1, a2, a3};
#pragma unroll
    for (int i = 0; i < 4; i++) {
        int r = brow + ty * 4 + i;
        if (r < n) {
            float4 o = accs[i];
            o.x += bv.x; o.y += bv.y; o.z += bv.z; o.w += bv.w;
            *(float4*)(g_h + r * D + tx * 4) = o;
            float4* pp = (float4*)(pool + r * D + tx * 4);
            if (addflag) {
                float4 p = *pp;
                p.x += o.x; p.y += o.y; p.z += o.z; p.w += o.w;
                *pp = p;
            } else {
                *pp = o;
            }
        }
    }
}

// ---------------- graph pooling (run-aware, batch sorted) -----------------
__global__ __launch_bounds__(256) void k_gpool(const float* __restrict__ np,
                                               const int* __restrict__ batch,
                                               float* __restrict__ gp, int n) {
    int col = threadIdx.x & 63;
    int rg  = threadIdx.x >> 6;  // 0..3
    int start = blockIdx.x * 1024;
    int end   = start + 1024;
    if (end > n) end = n;
    float acc = 0.f;
    int curb  = -1;
    for (int r = start + rg; r < end; r += 4) {
        int b = batch[r];
        if (b != curb) {
            if (curb >= 0) atomicAdd(&gp[curb * D + col], acc * g_invg[curb]);
            curb = b;
            acc  = 0.f;
        }
        acc += np[r * D + col];
    }
    if (curb >= 0) atomicAdd(&gp[curb * D + col], acc * g_invg[curb]);
}

// ---------------- launch (NO device-symbol references in host code!) ------
extern "C" void kernel_launch(void* const* d_in, const int* in_sizes, int n_in,
                              void* d_out, int out_size) {
    const float* x     = (const float*)d_in[0];
    const int*   ei    = (const int*)d_in[1];
    const int*   batch = (const int*)d_in[2];
    const float* W1    = (const float*)d_in[3];
    const float* b1    = (const float*)d_in[4];
    const float* gamma = (const float*)d_in[5];
    const float* beta  = (const float*)d_in[6];
    const float* W2    = (const float*)d_in[7];
    const float* b2    = (const float*)d_in[8];

    int n = in_sizes[0] / D;
    int e = in_sizes[1] / 2;
    int L = in_sizes[3] / (D * D);
    if (n > NCAP || e > ECAP || L > LCAP) return;

    float* np = (float*)d_out;
    float* gp = np + (size_t)n * D;
    int g = (out_size - n * D) / D;
    if (g > GCAP) return;

    const int* src = ei;
    const int* dst = ei + e;

    int eb256 = (e + 255) / 256;
    int nscan = (n + 1023) / 1024;

    int initN = n;
    if (g * D > initN) initN = g * D;
    if (L * 2 * D > initN) initN = L * 2 * D;

    k_init<<<(initN + 255) / 256, 256>>>(n, g, L, e, gp);
    k_degcnt<<<eb256, 256>>>(dst, batch, e, n);
    k_scan1<<<nscan, 256>>>(n, g);
    k_scan3<<<nscan, 256>>>(n, nscan);
    k_scatter<<<eb256, 256>>>(src, dst, e);

    int gemmBlocks = (n + 63) / 64;
    for (int l = 0; l < L; l++) {
        k_gemm0<<<gemmBlocks, 256>>>(x, W1 + l * D * D, b1 + l * D, l == 0 ? 1 : 0, l, n);
        k_gemm1<<<gemmBlocks, 256>>>(gamma + l * D, beta + l * D,
                                     W2 + l * D * D, b2 + l * D, np, l, n, l == 0 ? 0 : 1);
    }

    k_gpool<<<nscan, 256>>>(np, batch, gp, n);
}

// round 16
// speedup vs baseline: 1.3112x; 1.3112x over previous
#include <cuda_runtime.h>

#define D 64
#define NCAP 100000
#define ECAP 1600000
#define GCAP 128
#define LCAP 8
#define BN_EPS 1e-5f

// ---------------- device scratch ----------------
__device__ int   g_degcnt[NCAP];
__device__ int   g_off[NCAP + 1];
__device__ int   g_cur[NCAP];
__device__ int   g_csr[ECAP];
__device__ float g_invdeg[NCAP];
__device__ float g_gcnt[GCAP];
__device__ float g_invg[GCAP];
__device__ float g_h[NCAP * D];
__device__ float g_z[NCAP * D];
__device__ float g_statsall[LCAP * 2 * D];
__device__ int   g_bsum[128];

// ---------------- init: zero counters + stats + g_pool; off[n]=e ----------
__global__ void k_init(int n, int g, int L, int e, float* __restrict__ gp) {
    int i = blockIdx.x * blockDim.x + threadIdx.x;
    if (i < n) g_degcnt[i] = 0;
    if (i < g) g_gcnt[i] = 0.0f;
    if (i < g * D) gp[i] = 0.0f;
    if (i < L * 2 * D) g_statsall[i] = 0.0f;
    if (i == 0) g_off[n] = e;
}

// ---------------- fused histogram: in-degree + graph counts ----------------
__global__ void k_degcnt(const int* __restrict__ dst, const int* __restrict__ batch,
                         int e, int n) {
    int i = blockIdx.x * blockDim.x + threadIdx.x;
    if (i < e) atomicAdd(&g_degcnt[dst[i]], 1);
    if (i < n) atomicAdd(&g_gcnt[batch[i]], 1.0f);
}

// ---------------- scan pass 1: per-block reduce (1024/block) + invg -------
__global__ __launch_bounds__(256) void k_scan1(int n, int g) {
    int tid = threadIdx.x;
    int i0  = blockIdx.x * 1024 + tid * 4;
    int s = 0;
#pragma unroll
    for (int k = 0; k < 4; k++) {
        int i = i0 + k;
        if (i < n) s += g_degcnt[i];
    }
#pragma unroll
    for (int o = 16; o > 0; o >>= 1) s += __shfl_down_sync(0xffffffffu, s, o);
    __shared__ int ws[8];
    if ((tid & 31) == 0) ws[tid >> 5] = s;
    __syncthreads();
    if (tid == 0) {
        int t = 0;
#pragma unroll
        for (int k = 0; k < 8; k++) t += ws[k];
        g_bsum[blockIdx.x] = t;
    }
    if (blockIdx.x == 0 && tid < g) g_invg[tid] = 1.0f / fmaxf(g_gcnt[tid], 1.0f);
}

// ---------------- scan pass 2 (fused): local scan + inline predecessor sum
__global__ __launch_bounds__(256) void k_scan3(int n, int nblk) {
    int tid = threadIdx.x, lane = tid & 31, wid = tid >> 5;

    __shared__ int sPred;
    {
        int v = (tid < nblk && tid < blockIdx.x) ? g_bsum[tid] : 0;
#pragma unroll
        for (int o = 16; o > 0; o >>= 1) v += __shfl_down_sync(0xffffffffu, v, o);
        __shared__ int pw[8];
        if (lane == 0) pw[wid] = v;
        __syncthreads();
        if (tid == 0) {
            int t = 0;
#pragma unroll
            for (int k = 0; k < 8; k++) t += pw[k];
            sPred = t;
        }
    }

    int i0 = blockIdx.x * 1024 + tid * 4;
    int v[4];
#pragma unroll
    for (int k = 0; k < 4; k++) {
        int i = i0 + k;
        v[k] = (i < n) ? g_degcnt[i] : 0;
    }
    int s  = v[0] + v[1] + v[2] + v[3];
    int sc = s;
#pragma unroll
    for (int o = 1; o < 32; o <<= 1) {
        int t = __shfl_up_sync(0xffffffffu, sc, o);
        if (lane >= o) sc += t;
    }
    __shared__ int ws[8];
    if (lane == 31) ws[wid] = sc;
    __syncthreads();
    if (wid == 0) {
        int t = (lane < 8) ? ws[lane] : 0;
#pragma unroll
        for (int o = 1; o < 8; o <<= 1) {
            int u = __shfl_up_sync(0xffffffffu, t, o);
            if (lane >= o) t += u;
        }
        if (lane < 8) ws[lane] = t;
    }
    __syncthreads();
    int base = sPred + (wid ? ws[wid - 1] : 0) + (sc - s);
#pragma unroll
    for (int k = 0; k < 4; k++) {
        int i = i0 + k;
        if (i < n) {
            g_off[i]    = base;
            g_cur[i]    = base;
            g_invdeg[i] = 1.0f / fmaxf((float)v[k], 1.0f);
            base += v[k];
        }
    }
}

__global__ void k_scatter(const int* __restrict__ src, const int* __restrict__ dst, int e) {
    int i = blockIdx.x * blockDim.x + threadIdx.x;
    if (i < e) {
        int pos    = atomicAdd(&g_cur[dst[i]], 1);
        g_csr[pos] = src[i];
    }
}

// ---------------- GEMM0 fused: agg + GEMM + bias + BN stats (R11-exact) ---
__global__ __launch_bounds__(256) void k_gemm0(const float* __restrict__ x,
                                               const float* __restrict__ W,
                                               const float* __restrict__ bias,
                                               int first, int layer, int n) {
    __shared__ float sW[64 * 64];
    __shared__ float sX[64 * 68];
    int tid  = threadIdx.x;
    int brow = blockIdx.x * 64;
    int lane = tid & 31, wrp = tid >> 5;
    const float* __restrict__ hin = first ? x : (const float*)g_h;  // device-side
    float* __restrict__ stats = g_statsall + layer * 2 * D;         // device-side

    // stage W (coalesced)
    {
        const float4* W4 = (const float4*)W;
        float4* sW4      = (float4*)sW;
#pragma unroll
        for (int e = tid; e < 1024; e += 256) sW4[e] = W4[e];
    }

    // fused aggregation staging: warp handles 8 rows, lane owns 2 columns
    const float2* h2 = (const float2*)hin;
#pragma unroll 1
    for (int rr = 0; rr < 8; rr++) {
        int r   = wrp * 8 + rr;
        int row = brow + r;
        float2 a = make_float2(0.f, 0.f);
        if (row < n) {
            int beg = g_off[row], end = g_off[row + 1];
            for (int jb = beg; jb < end; jb += 32) {
                int cnt = end - jb;
                if (cnt > 32) cnt = 32;
                int sv = (lane < cnt) ? g_csr[jb + lane] : 0;
                for (int k = 0; k < cnt; k++) {
                    int s    = __shfl_sync(0xffffffffu, sv, k);
                    float2 v = h2[s * 32 + lane];
                    a.x += v.x;
                    a.y += v.y;
                }
            }
            float inv = g_invdeg[row];
            float2 hv = h2[row * 32 + lane];
            a.x = hv.x + a.x * inv;
            a.y = hv.y + a.y * inv;
        }
        sX[(2 * lane) * 68 + r]     = a.x;
        sX[(2 * lane + 1) * 68 + r] = a.y;
    }
    __syncthreads();

    int tx = tid & 15, ty = tid >> 4;
    float4 a0 = make_float4(0.f, 0.f, 0.f, 0.f), a1 = a0, a2 = a0, a3 = a0;
#pragma unroll
    for (int k = 0; k < 64; k++) {
        float4 w  = *(const float4*)&sW[k * 64 + tx * 4];
        float4 xv = *(const float4*)&sX[k * 68 + ty * 4];
        a0.x = fmaf(xv.x, w.x, a0.x); a0.y = fmaf(xv.x, w.y, a0.y);
        a0.z = fmaf(xv.x, w.z, a0.z); a0.w = fmaf(xv.x, w.w, a0.w);
        a1.x = fmaf(xv.y, w.x, a1.x); a1.y = fmaf(xv.y, w.y, a1.y);
        a1.z = fmaf(xv.y, w.z, a1.z); a1.w = fmaf(xv.y, w.w, a1.w);
        a2.x = fmaf(xv.z, w.x, a2.x); a2.y = fmaf(xv.z, w.y, a2.y);
        a2.z = fmaf(xv.z, w.z, a2.z); a2.w = fmaf(xv.z, w.w, a2.w);
        a3.x = fmaf(xv.w, w.x, a3.x); a3.y = fmaf(xv.w, w.y, a3.y);
        a3.z = fmaf(xv.w, w.z, a3.z); a3.w = fmaf(xv.w, w.w, a3.w);
    }

    float4 bv = *(const float4*)(bias + tx * 4);
    float4 accs[4] = {a0, a1, a2, a3};
    float4 s = make_float4(0.f, 0.f, 0.f, 0.f);
    float4 q = make_float4(0.f, 0.f, 0.f, 0.f);
#pragma unroll
    for (int i = 0; i < 4; i++) {
        int r = brow + ty * 4 + i;
        if (r < n) {
            float4 o = accs[i];
            o.x += bv.x; o.y += bv.y; o.z += bv.z; o.w += bv.w;
            *(float4*)(g_z + r * D + tx * 4) = o;
            s.x += o.x; s.y += o.y; s.z += o.z; s.w += o.w;
            q.x = fmaf(o.x, o.x, q.x); q.y = fmaf(o.y, o.y, q.y);
            q.z = fmaf(o.z, o.z, q.z); q.w = fmaf(o.w, o.w, q.w);
        }
    }
    __syncthreads();
    *(float4*)&sW[ty * 64 + tx * 4] = s;   // reuse smem: [16][64] partial sums
    *(float4*)&sX[ty * 64 + tx * 4] = q;
    __syncthreads();
    if (tid < 64) {
        float S = 0.f, Q = 0.f;
#pragma unroll
        for (int k = 0; k < 16; k++) {
            S += sW[k * 64 + tid];
            Q += sX[k * 64 + tid];
        }
        atomicAdd(&stats[tid], S);
        atomicAdd(&stats[64 + tid], Q);
    }
}

// ---------------- GEMM1: h = relu(bn(z)) @ W2 + b2, pool epilogue ---------
// LAST=0 instantiation is byte-identical to the proven R11 kernel.
// LAST=1 additionally performs run-aware graph pooling over this thread's
// 4 contiguous rows (batch is sorted), eliminating the k_gpool pass.
template <int LAST>
__global__ __launch_bounds__(256) void k_gemm1(const float* __restrict__ gamma,
                                               const float* __restrict__ beta,
                                               const float* __restrict__ W,
                                               const float* __restrict__ bias,
                                               float* __restrict__ pool,
                                               const int* __restrict__ batch,
                                               float* __restrict__ gp,
                                               int layer, int n, int addflag) {
    __shared__ float sW[64 * 64];
    __shared__ float sX[64 * 68];
    __shared__ float sAB[2 * D];
    int tid  = threadIdx.x;
    int brow = blockIdx.x * 64;
    const float* __restrict__ stats = g_statsall + layer * 2 * D;  // device-side

    if (tid < 64) {
        float invN = 1.0f / (float)n;
        float mean = stats[tid] * invN;
        float var  = stats[64 + tid] * invN - mean * mean;
        float a    = gamma[tid] * rsqrtf(var + BN_EPS);
        sAB[tid]      = a;
        sAB[64 + tid] = beta[tid] - mean * a;
    }
    {
        const float4* W4 = (const float4*)W;
        float4* sW4      = (float4*)sW;
#pragma unroll
        for (int e = tid; e < 1024; e += 256) sW4[e] = W4[e];
    }
    __syncthreads();

    for (int e = tid; e < 1024; e += 256) {
        int r   = e & 63;
        int c4  = e >> 6;
        int row = brow + r;
        float4 v = make_float4(0.f, 0.f, 0.f, 0.f);
        if (row < n) v = *(const float4*)(g_z + row * D + c4 * 4);
        int c = c4 * 4;
        v.x = fmaxf(fmaf(v.x, sAB[c + 0], sAB[64 + c + 0]), 0.f);
        v.y = fmaxf(fmaf(v.y, sAB[c + 1], sAB[64 + c + 1]), 0.f);
        v.z = fmaxf(fmaf(v.z, sAB[c + 2], sAB[64 + c + 2]), 0.f);
        v.w = fmaxf(fmaf(v.w, sAB[c + 3], sAB[64 + c + 3]), 0.f);
        sX[(c + 0) * 68 + r] = v.x;
        sX[(c + 1) * 68 + r] = v.y;
        sX[(c + 2) * 68 + r] = v.z;
        sX[(c + 3) * 68 + r] = v.w;
    }
    __syncthreads();

    int tx = tid & 15, ty = tid >> 4;
    float4 a0 = make_float4(0.f, 0.f, 0.f, 0.f), a1 = a0, a2 = a0, a3 = a0;
#pragma unroll
    for (int k = 0; k < 64; k++) {
        float4 w  = *(const float4*)&sW[k * 64 + tx * 4];
        float4 xv = *(const float4*)&sX[k * 68 + ty * 4];
        a0.x = fmaf(xv.x, w.x, a0.x); a0.y = fmaf(xv.x, w.y, a0.y);
        a0.z = fmaf(xv.x, w.z, a0.z); a0.w = fmaf(xv.x, w.w, a0.w);
        a1.x = fmaf(xv.y, w.x, a1.x); a1.y = fmaf(xv.y, w.y, a1.y);
        a1.z = fmaf(xv.y, w.z, a1.z); a1.w = fmaf(xv.y, w.w, a1.w);
        a2.x = fmaf(xv.z, w.x, a2.x); a2.y = fmaf(xv.z, w.y, a2.y);
        a2.z = fmaf(xv.z, w.z, a2.z); a2.w = fmaf(xv.z, w.w, a2.w);
        a3.x = fmaf(xv.w, w.x, a3.x); a3.y = fmaf(xv.w, w.y, a3.y);
        a3.z = fmaf(xv.w, w.z, a3.z); a3.w = fmaf(xv.w, w.w, a3.w);
    }

    float4 bv = *(const float4*)(bias + tx * 4);
    float4 accs[4] = {a0, a1, a2, a3};

    // run-aware pooling state (LAST only; rows of this thread are contiguous)
    float4 pacc = make_float4(0.f, 0.f, 0.f, 0.f);
    int curb = -1;

#pragma unroll
    for (int i = 0; i < 4; i++) {
        int r = brow + ty * 4 + i;
        if (r < n) {
            float4 o = accs[i];
            o.x += bv.x; o.y += bv.y; o.z += bv.z; o.w += bv.w;
            *(float4*)(g_h + r * D + tx * 4) = o;
            float4* pp = (float4*)(pool + r * D + tx * 4);
            float4 pv = o;
            if (addflag) {
                float4 p = *pp;
                pv.x += p.x; pv.y += p.y; pv.z += p.z; pv.w += p.w;
            }
            *pp = pv;
            if (LAST) {
                int b = batch[r];
                if (b != curb) {
                    if (curb >= 0) {
                        float ig = g_invg[curb];
                        atomicAdd(&gp[curb * D + tx * 4 + 0], pacc.x * ig);
                        atomicAdd(&gp[curb * D + tx * 4 + 1], pacc.y * ig);
                        atomicAdd(&gp[curb * D + tx * 4 + 2], pacc.z * ig);
                        atomicAdd(&gp[curb * D + tx * 4 + 3], pacc.w * ig);
                    }
                    curb = b;
                    pacc = make_float4(0.f, 0.f, 0.f, 0.f);
                }
                pacc.x += pv.x; pacc.y += pv.y; pacc.z += pv.z; pacc.w += pv.w;
            }
        }
    }
    if (LAST && curb >= 0) {
        float ig = g_invg[curb];
        atomicAdd(&gp[curb * D + tx * 4 + 0], pacc.x * ig);
        atomicAdd(&gp[curb * D + tx * 4 + 1], pacc.y * ig);
        atomicAdd(&gp[curb * D + tx * 4 + 2], pacc.z * ig);
        atomicAdd(&gp[curb * D + tx * 4 + 3], pacc.w * ig);
    }
}

// ---------------- launch (NO device-symbol references in host code!) ------
extern "C" void kernel_launch(void* const* d_in, const int* in_sizes, int n_in,
                              void* d_out, int out_size) {
    const float* x     = (const float*)d_in[0];
    const int*   ei    = (const int*)d_in[1];
    const int*   batch = (const int*)d_in[2];
    const float* W1    = (const float*)d_in[3];
    const float* b1    = (const float*)d_in[4];
    const float* gamma = (const float*)d_in[5];
    const float* beta  = (const float*)d_in[6];
    const float* W2    = (const float*)d_in[7];
    const float* b2    = (const float*)d_in[8];

    int n = in_sizes[0] / D;
    int e = in_sizes[1] / 2;
    int L = in_sizes[3] / (D * D);
    if (n > NCAP || e > ECAP || L > LCAP) return;

    float* np = (float*)d_out;
    float* gp = np + (size_t)n * D;
    int g = (out_size - n * D) / D;
    if (g > GCAP) return;

    const int* src = ei;
    const int* dst = ei + e;

    int eb256 = (e + 255) / 256;
    int nscan = (n + 1023) / 1024;

    int initN = n;
    if (g * D > initN) initN = g * D;
    if (L * 2 * D > initN) initN = L * 2 * D;

    k_init<<<(initN + 255) / 256, 256>>>(n, g, L, e, gp);
    k_degcnt<<<eb256, 256>>>(dst, batch, e, n);
    k_scan1<<<nscan, 256>>>(n, g);
    k_scan3<<<nscan, 256>>>(n, nscan);
    k_scatter<<<eb256, 256>>>(src, dst, e);

    int gemmBlocks = (n + 63) / 64;
    for (int l = 0; l < L; l++) {
        k_gemm0<<<gemmBlocks, 256>>>(x, W1 + l * D * D, b1 + l * D, l == 0 ? 1 : 0, l, n);
        if (l == L - 1) {
            k_gemm1<1><<<gemmBlocks, 256>>>(gamma + l * D, beta + l * D,
                                            W2 + l * D * D, b2 + l * D, np, batch, gp,
                                            l, n, l == 0 ? 0 : 1);
        } else {
            k_gemm1<0><<<gemmBlocks, 256>>>(gamma + l * D, beta + l * D,
                                            W2 + l * D * D, b2 + l * D, np, batch, gp,
                                            l, n, l == 0 ? 0 : 1);
        }
    }
}

// round 17
// speedup vs baseline: 1.3245x; 1.0102x over previous
#include <cuda_runtime.h>

#define D 64
#define NCAP 100000
#define ECAP 1600000
#define GCAP 128
#define LCAP 8
#define BN_EPS 1e-5f
#define ND (NCAP * D)

// ---------------- device scratch ----------------
__device__ int   g_degcnt[NCAP];
__device__ int   g_off[NCAP + 1];
__device__ int   g_cur[NCAP];
__device__ int   g_csr[ECAP];
__device__ float g_invdeg[NCAP];
__device__ float g_gcnt[GCAP];
__device__ float g_invg[GCAP];
__device__ float g_hist[LCAP * ND];   // per-layer h (replaces g_h + np RMW chain)
__device__ float g_z[ND];
__device__ float g_statsall[LCAP * 2 * D];
__device__ int   g_bsum[128];

// ---------------- init: zero counters + stats + g_pool; off[n]=e ----------
__global__ void k_init(int n, int g, int L, int e, float* __restrict__ gp) {
    int i = blockIdx.x * blockDim.x + threadIdx.x;
    if (i < n) g_degcnt[i] = 0;
    if (i < g) g_gcnt[i] = 0.0f;
    if (i < g * D) gp[i] = 0.0f;
    if (i < L * 2 * D) g_statsall[i] = 0.0f;
    if (i == 0) g_off[n] = e;
}

// ---------------- fused histogram: in-degree + graph counts ----------------
__global__ void k_degcnt(const int* __restrict__ dst, const int* __restrict__ batch,
                         int e, int n) {
    int i = blockIdx.x * blockDim.x + threadIdx.x;
    if (i < e) atomicAdd(&g_degcnt[dst[i]], 1);
    if (i < n) atomicAdd(&g_gcnt[batch[i]], 1.0f);
}

// ---------------- scan pass 1: per-block reduce (1024/block) + invg -------
__global__ __launch_bounds__(256) void k_scan1(int n, int g) {
    int tid = threadIdx.x;
    int i0  = blockIdx.x * 1024 + tid * 4;
    int s = 0;
#pragma unroll
    for (int k = 0; k < 4; k++) {
        int i = i0 + k;
        if (i < n) s += g_degcnt[i];
    }
#pragma unroll
    for (int o = 16; o > 0; o >>= 1) s += __shfl_down_sync(0xffffffffu, s, o);
    __shared__ int ws[8];
    if ((tid & 31) == 0) ws[tid >> 5] = s;
    __syncthreads();
    if (tid == 0) {
        int t = 0;
#pragma unroll
        for (int k = 0; k < 8; k++) t += ws[k];
        g_bsum[blockIdx.x] = t;
    }
    if (blockIdx.x == 0 && tid < g) g_invg[tid] = 1.0f / fmaxf(g_gcnt[tid], 1.0f);
}

// ---------------- scan pass 2 (fused): local scan + inline predecessor sum
__global__ __launch_bounds__(256) void k_scan3(int n, int nblk) {
    int tid = threadIdx.x, lane = tid & 31, wid = tid >> 5;

    __shared__ int sPred;
    {
        int v = (tid < nblk && tid < blockIdx.x) ? g_bsum[tid] : 0;
#pragma unroll
        for (int o = 16; o > 0; o >>= 1) v += __shfl_down_sync(0xffffffffu, v, o);
        __shared__ int pw[8];
        if (lane == 0) pw[wid] = v;
        __syncthreads();
        if (tid == 0) {
            int t = 0;
#pragma unroll
            for (int k = 0; k < 8; k++) t += pw[k];
            sPred = t;
        }
    }

    int i0 = blockIdx.x * 1024 + tid * 4;
    int v[4];
#pragma unroll
    for (int k = 0; k < 4; k++) {
        int i = i0 + k;
        v[k] = (i < n) ? g_degcnt[i] : 0;
    }
    int s  = v[0] + v[1] + v[2] + v[3];
    int sc = s;
#pragma unroll
    for (int o = 1; o < 32; o <<= 1) {
        int t = __shfl_up_sync(0xffffffffu, sc, o);
        if (lane >= o) sc += t;
    }
    __shared__ int ws[8];
    if (lane == 31) ws[wid] = sc;
    __syncthreads();
    if (wid == 0) {
        int t = (lane < 8) ? ws[lane] : 0;
#pragma unroll
        for (int o = 1; o < 8; o <<= 1) {
            int u = __shfl_up_sync(0xffffffffu, t, o);
            if (lane >= o) t += u;
        }
        if (lane < 8) ws[lane] = t;
    }
    __syncthreads();
    int base = sPred + (wid ? ws[wid - 1] : 0) + (sc - s);
#pragma unroll
    for (int k = 0; k < 4; k++) {
        int i = i0 + k;
        if (i < n) {
            g_off[i]    = base;
            g_cur[i]    = base;
            g_invdeg[i] = 1.0f / fmaxf((float)v[k], 1.0f);
            base += v[k];
        }
    }
}

__global__ void k_scatter(const int* __restrict__ src, const int* __restrict__ dst, int e) {
    int i = blockIdx.x * blockDim.x + threadIdx.x;
    if (i < e) {
        int pos    = atomicAdd(&g_cur[dst[i]], 1);
        g_csr[pos] = src[i];
    }
}

// ---------------- GEMM0 fused: agg + GEMM + bias + BN stats ---------------
// R11-exact; h input comes from g_hist[layer-1] (or x for layer 0).
__global__ __launch_bounds__(256) void k_gemm0(const float* __restrict__ x,
                                               const float* __restrict__ W,
                                               const float* __restrict__ bias,
                                               int first, int layer, int n) {
    __shared__ float sW[64 * 64];
    __shared__ float sX[64 * 68];
    int tid  = threadIdx.x;
    int brow = blockIdx.x * 64;
    int lane = tid & 31, wrp = tid >> 5;
    const float* __restrict__ hin = first ? x : (g_hist + (size_t)(layer - 1) * ND);
    float* __restrict__ stats = g_statsall + layer * 2 * D;

    // stage W (coalesced)
    {
        const float4* W4 = (const float4*)W;
        float4* sW4      = (float4*)sW;
#pragma unroll
        for (int e = tid; e < 1024; e += 256) sW4[e] = W4[e];
    }

    // fused aggregation staging: warp handles 8 rows, lane owns 2 columns
    const float2* h2 = (const float2*)hin;
#pragma unroll 1
    for (int rr = 0; rr < 8; rr++) {
        int r   = wrp * 8 + rr;
        int row = brow + r;
        float2 a = make_float2(0.f, 0.f);
        if (row < n) {
            int beg = g_off[row], end = g_off[row + 1];
            for (int jb = beg; jb < end; jb += 32) {
                int cnt = end - jb;
                if (cnt > 32) cnt = 32;
                int sv = (lane < cnt) ? g_csr[jb + lane] : 0;
                for (int k = 0; k < cnt; k++) {
                    int s    = __shfl_sync(0xffffffffu, sv, k);
                    float2 v = h2[s * 32 + lane];
                    a.x += v.x;
                    a.y += v.y;
                }
            }
            float inv = g_invdeg[row];
            float2 hv = h2[row * 32 + lane];
            a.x = hv.x + a.x * inv;
            a.y = hv.y + a.y * inv;
        }
        sX[(2 * lane) * 68 + r]     = a.x;
        sX[(2 * lane + 1) * 68 + r] = a.y;
    }
    __syncthreads();

    int tx = tid & 15, ty = tid >> 4;
    float4 a0 = make_float4(0.f, 0.f, 0.f, 0.f), a1 = a0, a2 = a0, a3 = a0;
#pragma unroll
    for (int k = 0; k < 64; k++) {
        float4 w  = *(const float4*)&sW[k * 64 + tx * 4];
        float4 xv = *(const float4*)&sX[k * 68 + ty * 4];
        a0.x = fmaf(xv.x, w.x, a0.x); a0.y = fmaf(xv.x, w.y, a0.y);
        a0.z = fmaf(xv.x, w.z, a0.z); a0.w = fmaf(xv.x, w.w, a0.w);
        a1.x = fmaf(xv.y, w.x, a1.x); a1.y = fmaf(xv.y, w.y, a1.y);
        a1.z = fmaf(xv.y, w.z, a1.z); a1.w = fmaf(xv.y, w.w, a1.w);
        a2.x = fmaf(xv.z, w.x, a2.x); a2.y = fmaf(xv.z, w.y, a2.y);
        a2.z = fmaf(xv.z, w.z, a2.z); a2.w = fmaf(xv.z, w.w, a2.w);
        a3.x = fmaf(xv.w, w.x, a3.x); a3.y = fmaf(xv.w, w.y, a3.y);
        a3.z = fmaf(xv.w, w.z, a3.z); a3.w = fmaf(xv.w, w.w, a3.w);
    }

    float4 bv = *(const float4*)(bias + tx * 4);
    float4 accs[4] = {a0, a1, a2, a3};
    float4 s = make_float4(0.f, 0.f, 0.f, 0.f);
    float4 q = make_float4(0.f, 0.f, 0.f, 0.f);
#pragma unroll
    for (int i = 0; i < 4; i++) {
        int r = brow + ty * 4 + i;
        if (r < n) {
            float4 o = accs[i];
            o.x += bv.x; o.y += bv.y; o.z += bv.z; o.w += bv.w;
            *(float4*)(g_z + r * D + tx * 4) = o;
            s.x += o.x; s.y += o.y; s.z += o.z; s.w += o.w;
            q.x = fmaf(o.x, o.x, q.x); q.y = fmaf(o.y, o.y, q.y);
            q.z = fmaf(o.z, o.z, q.z); q.w = fmaf(o.w, o.w, q.w);
        }
    }
    __syncthreads();
    *(float4*)&sW[ty * 64 + tx * 4] = s;   // reuse smem: [16][64] partial sums
    *(float4*)&sX[ty * 64 + tx * 4] = q;
    __syncthreads();
    if (tid < 64) {
        float S = 0.f, Q = 0.f;
#pragma unroll
        for (int k = 0; k < 16; k++) {
            S += sW[k * 64 + tid];
            Q += sX[k * 64 + tid];
        }
        atomicAdd(&stats[tid], S);
        atomicAdd(&stats[64 + tid], Q);
    }
}

// ---------------- GEMM1: h = relu(bn(z)) @ W2 + b2 ------------------------
// LAST=0: write h to g_hist[layer] only (no d_out traffic at all).
// LAST=1: np = h_L + sum(hist[0..L-2]) written once; fused run-aware pooling.
template <int LAST>
__global__ __launch_bounds__(256) void k_gemm1(const float* __restrict__ gamma,
                                               const float* __restrict__ beta,
                                               const float* __restrict__ W,
                                               const float* __restrict__ bias,
                                               float* __restrict__ np,
                                               const int* __restrict__ batch,
                                               float* __restrict__ gp,
                                               int layer, int n, int L) {
    __shared__ float sW[64 * 64];
    __shared__ float sX[64 * 68];
    __shared__ float sAB[2 * D];
    int tid  = threadIdx.x;
    int brow = blockIdx.x * 64;
    const float* __restrict__ stats = g_statsall + layer * 2 * D;

    if (tid < 64) {
        float invN = 1.0f / (float)n;
        float mean = stats[tid] * invN;
        float var  = stats[64 + tid] * invN - mean * mean;
        float a    = gamma[tid] * rsqrtf(var + BN_EPS);
        sAB[tid]      = a;
        sAB[64 + tid] = beta[tid] - mean * a;
    }
    {
        const float4* W4 = (const float4*)W;
        float4* sW4      = (float4*)sW;
#pragma unroll
        for (int e = tid; e < 1024; e += 256) sW4[e] = W4[e];
    }
    __syncthreads();

    for (int e = tid; e < 1024; e += 256) {
        int r   = e & 63;
        int c4  = e >> 6;
        int row = brow + r;
        float4 v = make_float4(0.f, 0.f, 0.f, 0.f);
        if (row < n) v = *(const float4*)(g_z + row * D + c4 * 4);
        int c = c4 * 4;
        v.x = fmaxf(fmaf(v.x, sAB[c + 0], sAB[64 + c + 0]), 0.f);
        v.y = fmaxf(fmaf(v.y, sAB[c + 1], sAB[64 + c + 1]), 0.f);
        v.z = fmaxf(fmaf(v.z, sAB[c + 2], sAB[64 + c + 2]), 0.f);
        v.w = fmaxf(fmaf(v.w, sAB[c + 3], sAB[64 + c + 3]), 0.f);
        sX[(c + 0) * 68 + r] = v.x;
        sX[(c + 1) * 68 + r] = v.y;
        sX[(c + 2) * 68 + r] = v.z;
        sX[(c + 3) * 68 + r] = v.w;
    }
    __syncthreads();

    int tx = tid & 15, ty = tid >> 4;
    float4 a0 = make_float4(0.f, 0.f, 0.f, 0.f), a1 = a0, a2 = a0, a3 = a0;
#pragma unroll
    for (int k = 0; k < 64; k++) {
        float4 w  = *(const float4*)&sW[k * 64 + tx * 4];
        float4 xv = *(const float4*)&sX[k * 68 + ty * 4];
        a0.x = fmaf(xv.x, w.x, a0.x); a0.y = fmaf(xv.x, w.y, a0.y);
        a0.z = fmaf(xv.x, w.z, a0.z); a0.w = fmaf(xv.x, w.w, a0.w);
        a1.x = fmaf(xv.y, w.x, a1.x); a1.y = fmaf(xv.y, w.y, a1.y);
        a1.z = fmaf(xv.y, w.z, a1.z); a1.w = fmaf(xv.y, w.w, a1.w);
        a2.x = fmaf(xv.z, w.x, a2.x); a2.y = fmaf(xv.z, w.y, a2.y);
        a2.z = fmaf(xv.z, w.z, a2.z); a2.w = fmaf(xv.z, w.w, a2.w);
        a3.x = fmaf(xv.w, w.x, a3.x); a3.y = fmaf(xv.w, w.y, a3.y);
        a3.z = fmaf(xv.w, w.z, a3.z); a3.w = fmaf(xv.w, w.w, a3.w);
    }

    float4 bv = *(const float4*)(bias + tx * 4);
    float4 accs[4] = {a0, a1, a2, a3};

    float* __restrict__ hout = g_hist + (size_t)layer * ND;

    // run-aware pooling state (LAST only; this thread's 4 rows are contiguous)
    float4 pacc = make_float4(0.f, 0.f, 0.f, 0.f);
    int curb = -1;

#pragma unroll
    for (int i = 0; i < 4; i++) {
        int r = brow + ty * 4 + i;
        if (r < n) {
            float4 o = accs[i];
            o.x += bv.x; o.y += bv.y; o.z += bv.z; o.w += bv.w;
            if (!LAST) {
                *(float4*)(hout + (size_t)r * D + tx * 4) = o;
            } else {
                // np = h_L + sum of previous layers' h
                float4 pv = o;
                for (int l = 0; l < L - 1; l++) {
                    float4 hv = *(const float4*)(g_hist + (size_t)l * ND + (size_t)r * D + tx * 4);
                    pv.x += hv.x; pv.y += hv.y; pv.z += hv.z; pv.w += hv.w;
                }
                *(float4*)(np + (size_t)r * D + tx * 4) = pv;
                int b = batch[r];
                if (b != curb) {
                    if (curb >= 0) {
                        float ig = g_invg[curb];
                        atomicAdd(&gp[curb * D + tx * 4 + 0], pacc.x * ig);
                        atomicAdd(&gp[curb * D + tx * 4 + 1], pacc.y * ig);
                        atomicAdd(&gp[curb * D + tx * 4 + 2], pacc.z * ig);
                        atomicAdd(&gp[curb * D + tx * 4 + 3], pacc.w * ig);
                    }
                    curb = b;
                    pacc = make_float4(0.f, 0.f, 0.f, 0.f);
                }
                pacc.x += pv.x; pacc.y += pv.y; pacc.z += pv.z; pacc.w += pv.w;
            }
        }
    }
    if (LAST && curb >= 0) {
        float ig = g_invg[curb];
        atomicAdd(&gp[curb * D + tx * 4 + 0], pacc.x * ig);
        atomicAdd(&gp[curb * D + tx * 4 + 1], pacc.y * ig);
        atomicAdd(&gp[curb * D + tx * 4 + 2], pacc.z * ig);
        atomicAdd(&gp[curb * D + tx * 4 + 3], pacc.w * ig);
    }
}

// ---------------- launch (NO device-symbol references in host code!) ------
extern "C" void kernel_launch(void* const* d_in, const int* in_sizes, int n_in,
                              void* d_out, int out_size) {
    const float* x     = (const float*)d_in[0];
    const int*   ei    = (const int*)d_in[1];
    const int*   batch = (const int*)d_in[2];
    const float* W1    = (const float*)d_in[3];
    const float* b1    = (const float*)d_in[4];
    const float* gamma = (const float*)d_in[5];
    const float* beta  = (const float*)d_in[6];
    const float* W2    = (const float*)d_in[7];
    const float* b2    = (const float*)d_in[8];

    int n = in_sizes[0] / D;
    int e = in_sizes[1] / 2;
    int L = in_sizes[3] / (D * D);
    if (n > NCAP || e > ECAP || L > LCAP) return;

    float* np = (float*)d_out;
    float* gp = np + (size_t)n * D;
    int g = (out_size - n * D) / D;
    if (g > GCAP) return;

    const int* src = ei;
    const int* dst = ei + e;

    int eb256 = (e + 255) / 256;
    int nscan = (n + 1023) / 1024;

    int initN = n;
    if (g * D > initN) initN = g * D;
    if (L * 2 * D > initN) initN = L * 2 * D;

    k_init<<<(initN + 255) / 256, 256>>>(n, g, L, e, gp);
    k_degcnt<<<eb256, 256>>>(dst, batch, e, n);
    k_scan1<<<nscan, 256>>>(n, g);
    k_scan3<<<nscan, 256>>>(n, nscan);
    k_scatter<<<eb256, 256>>>(src, dst, e);

    int gemmBlocks = (n + 63) / 64;
    for (int l = 0; l < L; l++) {
        k_gemm0<<<gemmBlocks, 256>>>(x, W1 + l * D * D, b1 + l * D, l == 0 ? 1 : 0, l, n);
        if (l == L - 1) {
            k_gemm1<1><<<gemmBlocks, 256>>>(gamma + l * D, beta + l * D,
                                            W2 + l * D * D, b2 + l * D, np, batch, gp,
                                            l, n, L);
        } else {
            k_gemm1<0><<<gemmBlocks, 256>>>(gamma + l * D, beta + l * D,
                                            W2 + l * D * D, b2 + l * D, np, batch, gp,
                                            l, n, L);
        }
    }
}